// round 11
// baseline (speedup 1.0000x reference)
#include <cuda_runtime.h>

#define BB 64
#define SS 129
#define FF 768
#define DD 4
#define KDIM (SS*FF)
#define N3 (3*BB)
#define MOM 0.9f
#define EPSV 1e-6f

#define XMIX_N (BB*SS*FF)
#define LOSS_OFF XMIX_N
#define NM_OFF (XMIX_N + 1)
#define NV_OFF (NM_OFF + DD*FF)

#define KSPLIT 144
#define SROW 36
#define BUF_ELEMS (N3*SROW)
#define NPAIR 6
#define PAIRSZ 4096
#define KSLAB (NPAIR*PAIRSZ)

__device__ float g_pA1[4][BB*FF];
__device__ float g_pA2[4][BB*FF];
__device__ float g_mu[BB*FF];
__device__ float g_inv[BB*FF];
__device__ float g_nm[DD*FF];
__device__ float g_nsd[DD*FF];
__device__ float g_gpart[KSPLIT*KSLAB];
__device__ float g_part2[8][KSLAB];
__device__ float g_G[N3*N3];
__device__ float g_rowloss[N3];

__device__ __forceinline__ unsigned tf32r(float v) {
    unsigned r;
    asm("cvt.rna.tf32.f32 %0, %1;" : "=r"(r) : "f"(v));
    return r;
}

__device__ __forceinline__ void mma_tf32(float* d, const unsigned* a, const unsigned* b) {
    asm volatile("mma.sync.aligned.m16n8k8.row.col.f32.tf32.tf32.f32 "
        "{%0,%1,%2,%3},{%4,%5,%6,%7},{%8,%9},{%0,%1,%2,%3};"
        : "+f"(d[0]), "+f"(d[1]), "+f"(d[2]), "+f"(d[3])
        : "r"(a[0]), "r"(a[1]), "r"(a[2]), "r"(a[3]), "r"(b[0]), "r"(b[1]));
}

__global__ void stageA1(const float* __restrict__ x) {
    int bf = blockIdx.x;
    int seg = blockIdx.y;
    int b = bf / 3;
    int f = (bf % 3) * 256 + threadIdx.x;
    int s0 = (seg == 0) ? 0 : 33 + 32 * (seg - 1);
    int s1 = 33 + 32 * seg;
    const float* p = x + (size_t)b * KDIM + f;
    float sa = 0.f, sb2 = 0.f, sc = 0.f, sd2 = 0.f;
    int ss = s0;
    for (; ss + 1 < s1; ss += 2) {
        float v0 = p[(size_t)ss * FF];
        float v1 = p[(size_t)(ss + 1) * FF];
        sa += v0; sb2 += v0 * v0;
        sc += v1; sd2 += v1 * v1;
    }
    if (ss < s1) { float v = p[(size_t)ss * FF]; sa += v; sb2 += v * v; }
    int o = b * FF + f;
    g_pA1[seg][o] = sa + sc;
    g_pA2[seg][o] = sb2 + sd2;
}

__global__ void stageAB(const float* __restrict__ mean_buf,
                        const float* __restrict__ var_buf,
                        const int* __restrict__ domain,
                        float* __restrict__ out) {
    __shared__ float s1s[64][65];
    __shared__ float s2s[64][65];
    __shared__ int doms[64];
    int tid = threadIdx.x;
    int f0 = blockIdx.x * 64;
    if (tid < 64) doms[tid] = domain[tid];
    #pragma unroll
    for (int i = 0; i < 16; i++) {
        int e = tid + 256 * i;
        int b = e >> 6, f = e & 63;
        int idx = b * FF + f0 + f;
        float s  = g_pA1[0][idx] + g_pA1[1][idx] + g_pA1[2][idx] + g_pA1[3][idx];
        float s2 = g_pA2[0][idx] + g_pA2[1][idx] + g_pA2[2][idx] + g_pA2[3][idx];
        float mu = s / (float)SS;
        float var = (s2 - (float)SS * mu * mu) / (float)(SS - 1);
        g_mu[idx] = mu;
        g_inv[idx] = rsqrtf(var + EPSV);
        s1s[b][f] = s;
        s2s[b][f] = s2;
    }
    __syncthreads();
    int d = tid >> 6, f = tid & 63;
    float s1 = 0.f, s2 = 0.f;
    int nb = 0;
    #pragma unroll 8
    for (int b = 0; b < BB; b++) {
        if (doms[b] == d) {
            nb++;
            s1 += s1s[b][f];
            s2 += s2s[b][f];
        }
    }
    float n = (float)nb * (float)SS;
    float mu = s1 / fmaxf(n, 1.f);
    float var = (s2 - n * mu * mu) / fmaxf(n - 1.f, 1.f);
    int idx = d * FF + f0 + f;
    float nm, nv;
    if (nb > 0) {
        nm = MOM * mean_buf[idx] + (1.f - MOM) * mu;
        nv = MOM * var_buf[idx] + (1.f - MOM) * var;
    } else {
        nm = mean_buf[idx];
        nv = var_buf[idx];
    }
    out[NM_OFF + idx] = nm;
    out[NV_OFF + idx] = nv;
    g_nm[idx] = nm;
    g_nsd[idx] = sqrtf(nv + EPSV);
}

// grid (144, 2): x = k-chunk, y = pair-half. 256 threads, 2 CTAs/SM.
// half 0 computes pairs (0,0)(0,1)(0,2) and writes xmix; half 1: (1,1)(1,2)(2,2).
__global__ __launch_bounds__(256, 2)
void gram_tc(const float* __restrict__ x,
             const float* __restrict__ hgn,
             const float* __restrict__ lmda,
             const int* __restrict__ domain,
             const int* __restrict__ drand,
             float* __restrict__ out) {
    extern __shared__ unsigned sbuf[];
    int tid = threadIdx.x;
    int ks = blockIdx.x;
    int half = blockIdx.y;
    int start = ks * 21 + (ks < 72 ? ks : 72);
    int ntile = (ks < 72) ? 22 : 21;
    long kbase = (long)start * 32;

    int r = tid >> 3, q = tid & 7;
    const float* px0 = x   + (size_t)r        * KDIM + kbase + q * 4;
    const float* px1 = x   + (size_t)(r + 32) * KDIM + kbase + q * 4;
    const float* ph0 = hgn + (size_t)r        * KDIM + kbase + q * 4;
    const float* ph1 = hgn + (size_t)(r + 32) * KDIM + kbase + q * 4;
    float* op0 = out + (size_t)r        * KDIM + kbase + q * 4;
    float* op1 = out + (size_t)(r + 32) * KDIM + kbase + q * 4;
    float lm0 = lmda[r], lm1 = lmda[r + 32];
    int dom0 = domain[r], dom1 = domain[r + 32];
    int ds0 = (dom0 + drand[r]) & 3, ds1 = (dom1 + drand[r + 32]) & 3;
    int q4 = q * 4;
    int offm0 = r * FF + q4, offm1 = (r + 32) * FF + q4;
    int offdx0 = ds0 * FF + q4, offdx1 = ds1 * FF + q4;
    int offdh0 = dom0 * FF + q4, offdh1 = dom1 * FF + q4;
    int sb0 = r * SROW + q4;

    int wid = tid >> 5, lane = tid & 31;
    int wm = wid >> 2, wn = wid & 3;
    int lr = lane >> 2, lc = lane & 3;
    float acc[3][2][2][4];
    #pragma unroll
    for (int pp = 0; pp < 3; pp++)
        #pragma unroll
        for (int mt = 0; mt < 2; mt++)
            #pragma unroll
            for (int nt = 0; nt < 2; nt++)
                #pragma unroll
                for (int rr = 0; rr < 4; rr++) acc[pp][mt][nt][rr] = 0.f;

    int fm = start % 24;

    for (int t = 0; t < ntile; t++) {
        unsigned* bb = sbuf + (t & 1) * BUF_ELEMS;
        int fo = fm * 32;
        fm = (fm + 1 == 24) ? 0 : fm + 1;
        int t32 = t * 32;
        float4 xa = *(const float4*)(px0 + t32);
        float4 xb = *(const float4*)(px1 + t32);
        float4 ha = *(const float4*)(ph0 + t32);
        float4 hb = *(const float4*)(ph1 + t32);
        float4 mu0 = *(const float4*)(g_mu  + offm0  + fo);
        float4 iv0 = *(const float4*)(g_inv + offm0  + fo);
        float4 nm0 = *(const float4*)(g_nm  + offdx0 + fo);
        float4 sd0 = *(const float4*)(g_nsd + offdx0 + fo);
        float il0 = 1.f - lm0;
        float4 xma;
        xma.x = lm0 * xa.x + il0 * fmaf((xa.x - mu0.x) * iv0.x, sd0.x, nm0.x);
        xma.y = lm0 * xa.y + il0 * fmaf((xa.y - mu0.y) * iv0.y, sd0.y, nm0.y);
        xma.z = lm0 * xa.z + il0 * fmaf((xa.z - mu0.z) * iv0.z, sd0.z, nm0.z);
        xma.w = lm0 * xa.w + il0 * fmaf((xa.w - mu0.w) * iv0.w, sd0.w, nm0.w);
        float4 mu1 = *(const float4*)(g_mu  + offm1  + fo);
        float4 iv1 = *(const float4*)(g_inv + offm1  + fo);
        float4 nm1 = *(const float4*)(g_nm  + offdx1 + fo);
        float4 sd1 = *(const float4*)(g_nsd + offdx1 + fo);
        float il1 = 1.f - lm1;
        float4 xmb;
        xmb.x = lm1 * xb.x + il1 * fmaf((xb.x - mu1.x) * iv1.x, sd1.x, nm1.x);
        xmb.y = lm1 * xb.y + il1 * fmaf((xb.y - mu1.y) * iv1.y, sd1.y, nm1.y);
        xmb.z = lm1 * xb.z + il1 * fmaf((xb.z - mu1.z) * iv1.z, sd1.z, nm1.z);
        xmb.w = lm1 * xb.w + il1 * fmaf((xb.w - mu1.w) * iv1.w, sd1.w, nm1.w);
        if (half == 0) {
            *(float4*)(op0 + t32) = xma;
            *(float4*)(op1 + t32) = xmb;
        }
        float4 nh0 = *(const float4*)(g_nm  + offdh0 + fo);
        float4 sh0 = *(const float4*)(g_nsd + offdh0 + fo);
        float4 hga;
        hga.x = fmaf(sh0.x, ha.x, nh0.x);
        hga.y = fmaf(sh0.y, ha.y, nh0.y);
        hga.z = fmaf(sh0.z, ha.z, nh0.z);
        hga.w = fmaf(sh0.w, ha.w, nh0.w);
        float4 nh1 = *(const float4*)(g_nm  + offdh1 + fo);
        float4 sh1 = *(const float4*)(g_nsd + offdh1 + fo);
        float4 hgb;
        hgb.x = fmaf(sh1.x, hb.x, nh1.x);
        hgb.y = fmaf(sh1.y, hb.y, nh1.y);
        hgb.z = fmaf(sh1.z, hb.z, nh1.z);
        hgb.w = fmaf(sh1.w, hb.w, nh1.w);
        uint4 u;
        u.x = tf32r(xa.x); u.y = tf32r(xa.y); u.z = tf32r(xa.z); u.w = tf32r(xa.w);
        *(uint4*)(&bb[sb0]) = u;
        u.x = tf32r(xb.x); u.y = tf32r(xb.y); u.z = tf32r(xb.z); u.w = tf32r(xb.w);
        *(uint4*)(&bb[sb0 + 32 * SROW]) = u;
        u.x = tf32r(xma.x); u.y = tf32r(xma.y); u.z = tf32r(xma.z); u.w = tf32r(xma.w);
        *(uint4*)(&bb[sb0 + 64 * SROW]) = u;
        u.x = tf32r(xmb.x); u.y = tf32r(xmb.y); u.z = tf32r(xmb.z); u.w = tf32r(xmb.w);
        *(uint4*)(&bb[sb0 + 96 * SROW]) = u;
        u.x = tf32r(hga.x); u.y = tf32r(hga.y); u.z = tf32r(hga.z); u.w = tf32r(hga.w);
        *(uint4*)(&bb[sb0 + 128 * SROW]) = u;
        u.x = tf32r(hgb.x); u.y = tf32r(hgb.y); u.z = tf32r(hgb.z); u.w = tf32r(hgb.w);
        *(uint4*)(&bb[sb0 + 160 * SROW]) = u;
        __syncthreads();
        const unsigned* S = bb;
        if (half == 0) {
            #pragma unroll
            for (int kk = 0; kk < 4; kk++) {
                int k0 = kk * 8;
                unsigned af[2][4], bfr[3][2][2];
                #pragma unroll
                for (int mt = 0; mt < 2; mt++) {
                    int r0 = wm * 32 + mt * 16 + lr;
                    af[mt][0] = S[r0 * SROW + k0 + lc];
                    af[mt][1] = S[(r0 + 8) * SROW + k0 + lc];
                    af[mt][2] = S[r0 * SROW + k0 + lc + 4];
                    af[mt][3] = S[(r0 + 8) * SROW + k0 + lc + 4];
                }
                #pragma unroll
                for (int g = 0; g < 3; g++)
                    #pragma unroll
                    for (int nt = 0; nt < 2; nt++) {
                        int n0 = g * 64 + wn * 16 + nt * 8 + lr;
                        bfr[g][nt][0] = S[n0 * SROW + k0 + lc];
                        bfr[g][nt][1] = S[n0 * SROW + k0 + lc + 4];
                    }
                #pragma unroll
                for (int pp = 0; pp < 3; pp++)
                    #pragma unroll
                    for (int mt = 0; mt < 2; mt++)
                        #pragma unroll
                        for (int nt = 0; nt < 2; nt++)
                            mma_tf32(acc[pp][mt][nt], af[mt], bfr[pp][nt]);
            }
        } else {
            #pragma unroll
            for (int kk = 0; kk < 4; kk++) {
                int k0 = kk * 8;
                unsigned af[2][2][4], bfr[2][2][2];
                #pragma unroll
                for (int ga = 0; ga < 2; ga++)
                    #pragma unroll
                    for (int mt = 0; mt < 2; mt++) {
                        int r0 = (ga + 1) * 64 + wm * 32 + mt * 16 + lr;
                        af[ga][mt][0] = S[r0 * SROW + k0 + lc];
                        af[ga][mt][1] = S[(r0 + 8) * SROW + k0 + lc];
                        af[ga][mt][2] = S[r0 * SROW + k0 + lc + 4];
                        af[ga][mt][3] = S[(r0 + 8) * SROW + k0 + lc + 4];
                    }
                #pragma unroll
                for (int gb = 0; gb < 2; gb++)
                    #pragma unroll
                    for (int nt = 0; nt < 2; nt++) {
                        int n0 = (gb + 1) * 64 + wn * 16 + nt * 8 + lr;
                        bfr[gb][nt][0] = S[n0 * SROW + k0 + lc];
                        bfr[gb][nt][1] = S[n0 * SROW + k0 + lc + 4];
                    }
                const int PA[3] = {0, 0, 1};
                const int PB[3] = {0, 1, 1};
                #pragma unroll
                for (int pp = 0; pp < 3; pp++)
                    #pragma unroll
                    for (int mt = 0; mt < 2; mt++)
                        #pragma unroll
                        for (int nt = 0; nt < 2; nt++)
                            mma_tf32(acc[pp][mt][nt], af[PA[pp]][mt], bfr[PB[pp]][nt]);
            }
        }
    }

    float* base = g_gpart + (size_t)ks * KSLAB + (half * 3) * PAIRSZ;
    #pragma unroll
    for (int pp = 0; pp < 3; pp++) {
        #pragma unroll
        for (int mt = 0; mt < 2; mt++) {
            #pragma unroll
            for (int nt = 0; nt < 2; nt++) {
                int rr = wm * 32 + mt * 16 + lr;
                int c = wn * 16 + nt * 8 + lc * 2;
                float* dst = base + pp * PAIRSZ + rr * 64 + c;
                *(float2*)dst = make_float2(acc[pp][mt][nt][0], acc[pp][mt][nt][1]);
                *(float2*)(dst + 8 * 64) = make_float2(acc[pp][mt][nt][2], acc[pp][mt][nt][3]);
            }
        }
    }
}

__global__ void reduceG1() {
    int i4 = (blockIdx.x * 256 + threadIdx.x) * 4;
    int c = blockIdx.y;
    const float* src = g_gpart + (size_t)(c * 18) * KSLAB + i4;
    float4 v[18];
    #pragma unroll
    for (int p = 0; p < 18; p++)
        v[p] = *(const float4*)(src + (size_t)p * KSLAB);
    #pragma unroll
    for (int p = 0; p < 9; p++) {
        v[p].x += v[p + 9].x; v[p].y += v[p + 9].y;
        v[p].z += v[p + 9].z; v[p].w += v[p + 9].w;
    }
    #pragma unroll
    for (int p = 0; p < 4; p++) {
        v[p].x += v[p + 4].x; v[p].y += v[p + 4].y;
        v[p].z += v[p + 4].z; v[p].w += v[p + 4].w;
    }
    v[0].x += v[8].x; v[0].y += v[8].y; v[0].z += v[8].z; v[0].w += v[8].w;
    #pragma unroll
    for (int p = 0; p < 2; p++) {
        v[p].x += v[p + 2].x; v[p].y += v[p + 2].y;
        v[p].z += v[p + 2].z; v[p].w += v[p + 2].w;
    }
    v[0].x += v[1].x; v[0].y += v[1].y; v[0].z += v[1].z; v[0].w += v[1].w;
    *(float4*)(&g_part2[c][i4]) = v[0];
}

__global__ void reduceG2() {
    int idx = blockIdx.x * 256 + threadIdx.x;
    if (idx >= N3 * N3) return;
    int i = idx / N3, j = idx % N3;
    int ti = i >> 6, tj = j >> 6, li = i & 63, lj = j & 63;
    int a, b2, la, lb;
    if (ti <= tj) { a = ti; b2 = tj; la = li; lb = lj; }
    else          { a = tj; b2 = ti; la = lj; lb = li; }
    int pair = a * (5 - a) / 2 + b2;
    int o = pair * PAIRSZ + la * 64 + lb;
    float s = 0.f;
    #pragma unroll
    for (int c = 0; c < 8; c++) s += g_part2[c][o];
    g_G[idx] = s;
}

__global__ void lossA(const int* __restrict__ labels) {
    int i = (blockIdx.x * blockDim.x + threadIdx.x) >> 5;
    int lane = threadIdx.x & 31;
    int li = (i < 2 * BB) ? labels[i & 63] : -1;
    float sqi = g_G[i * N3 + i];
    float ap = -1e30f, an = 1e30f;
    #pragma unroll
    for (int jj = 0; jj < 6; jj++) {
        int j = lane + jj * 32;
        int lj = (j < 2 * BB) ? labels[j & 63] : -1;
        float d2 = sqi + g_G[j * N3 + j] - 2.f * g_G[i * N3 + j];
        float dd = sqrtf(fmaxf(d2, 1e-12f));
        if (li == lj) ap = fmaxf(ap, dd);
        else          an = fminf(an, dd);
    }
    #pragma unroll
    for (int o = 16; o > 0; o >>= 1) {
        ap = fmaxf(ap, __shfl_xor_sync(0xFFFFFFFFu, ap, o));
        an = fminf(an, __shfl_xor_sync(0xFFFFFFFFu, an, o));
    }
    if (lane == 0) {
        float z = ap - an;
        g_rowloss[i] = (z > 0.f) ? (z + log1pf(expf(-z))) : log1pf(expf(z));
    }
}

__global__ void lossB(float* __restrict__ out) {
    __shared__ float red[256];
    int t = threadIdx.x;
    red[t] = (t < N3) ? g_rowloss[t] : 0.f;
    __syncthreads();
    for (int st = 128; st > 0; st >>= 1) {
        if (t < st) red[t] += red[t + st];
        __syncthreads();
    }
    if (t == 0) out[LOSS_OFF] = red[0] / (float)N3;
}

extern "C" void kernel_launch(void* const* d_in, const int* in_sizes, int n_in,
                              void* d_out, int out_size) {
    const float* x        = (const float*)d_in[0];
    const float* lmda     = (const float*)d_in[1];
    const float* mean_buf = (const float*)d_in[2];
    const float* var_buf  = (const float*)d_in[3];
    const float* hgn      = (const float*)d_in[4];
    const int*   labels   = (const int*)d_in[5];
    const int*   domain   = (const int*)d_in[6];
    const int*   d_rand   = (const int*)d_in[7];
    float* out = (float*)d_out;

    int smem_sz = 2 * BUF_ELEMS * (int)sizeof(unsigned);
    cudaFuncSetAttribute(gram_tc, cudaFuncAttributeMaxDynamicSharedMemorySize, smem_sz);

    dim3 ga(BB * 3, 4);
    stageA1<<<ga, 256>>>(x);
    stageAB<<<FF / 64, 256>>>(mean_buf, var_buf, domain, out);
    dim3 gg(KSPLIT, 2);
    gram_tc<<<gg, 256, smem_sz>>>(x, hgn, lmda, domain, d_rand, out);
    dim3 gr(KSLAB / 1024, 8);
    reduceG1<<<gr, 256>>>();
    reduceG2<<<(N3 * N3 + 255) / 256, 256>>>();
    lossA<<<N3 / 8, 256>>>(labels);
    lossB<<<1, 256>>>(out);
}

// round 12
// speedup vs baseline: 1.1492x; 1.1492x over previous
#include <cuda_runtime.h>

#define BB 64
#define SS 129
#define FF 768
#define DD 4
#define KDIM (SS*FF)
#define N3 (3*BB)
#define MOM 0.9f
#define EPSV 1e-6f

#define XMIX_N (BB*SS*FF)
#define LOSS_OFF XMIX_N
#define NM_OFF (XMIX_N + 1)
#define NV_OFF (NM_OFF + DD*FF)

// gram config: bf16 tiles, k-chunk 768 per CTA
#define KSPLIT 129
#define NTILES 24
#define SROWB 20                    // u32 (bf16x2) units per 32-k row, padded
#define BUFB (N3*SROWB)             // 3840 u32 per buffer
#define NPAIR 6
#define PAIRSZ 4096
#define KSLAB (NPAIR*PAIRSZ)
#define RCHUNK 16                   // reduce stage-1 chunks

__device__ float g_pA1[4][BB*FF];
__device__ float g_pA2[4][BB*FF];
__device__ float g_mu[BB*FF];
__device__ float g_inv[BB*FF];
__device__ float g_nm[DD*FF];
__device__ float g_nsd[DD*FF];
__device__ float g_gpart[KSPLIT*KSLAB];
__device__ float g_part2[RCHUNK][KSLAB];
__device__ float g_G[N3*N3];
__device__ float g_rowloss[N3];

__device__ __forceinline__ unsigned bfx2(float lo, float hi) {
    unsigned r;
    asm("cvt.rn.bf16x2.f32 %0, %1, %2;" : "=r"(r) : "f"(hi), "f"(lo));
    return r;
}

__device__ __forceinline__ void mma_bf16(float* d, const unsigned* a, const unsigned* b) {
    asm volatile("mma.sync.aligned.m16n8k16.row.col.f32.bf16.bf16.f32 "
        "{%0,%1,%2,%3},{%4,%5,%6,%7},{%8,%9},{%0,%1,%2,%3};"
        : "+f"(d[0]), "+f"(d[1]), "+f"(d[2]), "+f"(d[3])
        : "r"(a[0]), "r"(a[1]), "r"(a[2]), "r"(a[3]), "r"(b[0]), "r"(b[1]));
}

__global__ void stageA1(const float* __restrict__ x) {
    int bf = blockIdx.x;
    int seg = blockIdx.y;
    int b = bf / 3;
    int f = (bf % 3) * 256 + threadIdx.x;
    int s0 = (seg == 0) ? 0 : 33 + 32 * (seg - 1);
    int s1 = 33 + 32 * seg;
    const float* p = x + (size_t)b * KDIM + f;
    float sa = 0.f, sb2 = 0.f, sc = 0.f, sd2 = 0.f;
    int ss = s0;
    for (; ss + 1 < s1; ss += 2) {
        float v0 = p[(size_t)ss * FF];
        float v1 = p[(size_t)(ss + 1) * FF];
        sa += v0; sb2 += v0 * v0;
        sc += v1; sd2 += v1 * v1;
    }
    if (ss < s1) { float v = p[(size_t)ss * FF]; sa += v; sb2 += v * v; }
    int o = b * FF + f;
    g_pA1[seg][o] = sa + sc;
    g_pA2[seg][o] = sb2 + sd2;
}

__global__ void stageAB(const float* __restrict__ mean_buf,
                        const float* __restrict__ var_buf,
                        const int* __restrict__ domain,
                        float* __restrict__ out) {
    __shared__ float s1s[64][65];
    __shared__ float s2s[64][65];
    __shared__ int doms[64];
    int tid = threadIdx.x;
    int f0 = blockIdx.x * 64;
    if (tid < 64) doms[tid] = domain[tid];
    #pragma unroll
    for (int i = 0; i < 16; i++) {
        int e = tid + 256 * i;
        int b = e >> 6, f = e & 63;
        int idx = b * FF + f0 + f;
        float s  = g_pA1[0][idx] + g_pA1[1][idx] + g_pA1[2][idx] + g_pA1[3][idx];
        float s2 = g_pA2[0][idx] + g_pA2[1][idx] + g_pA2[2][idx] + g_pA2[3][idx];
        float mu = s / (float)SS;
        float var = (s2 - (float)SS * mu * mu) / (float)(SS - 1);
        g_mu[idx] = mu;
        g_inv[idx] = rsqrtf(var + EPSV);
        s1s[b][f] = s;
        s2s[b][f] = s2;
    }
    __syncthreads();
    int d = tid >> 6, f = tid & 63;
    float s1 = 0.f, s2 = 0.f;
    int nb = 0;
    #pragma unroll 8
    for (int b = 0; b < BB; b++) {
        if (doms[b] == d) {
            nb++;
            s1 += s1s[b][f];
            s2 += s2s[b][f];
        }
    }
    float n = (float)nb * (float)SS;
    float mu = s1 / fmaxf(n, 1.f);
    float var = (s2 - n * mu * mu) / fmaxf(n - 1.f, 1.f);
    int idx = d * FF + f0 + f;
    float nm, nv;
    if (nb > 0) {
        nm = MOM * mean_buf[idx] + (1.f - MOM) * mu;
        nv = MOM * var_buf[idx] + (1.f - MOM) * var;
    } else {
        nm = mean_buf[idx];
        nv = var_buf[idx];
    }
    out[NM_OFF + idx] = nm;
    out[NV_OFF + idx] = nv;
    g_nm[idx] = nm;
    g_nsd[idx] = sqrtf(nv + EPSV);
}

// fused gram (bf16 mma m16n8k16) + xmix + hg.
// 129 CTAs x 256 threads. Loader: 6 quad-elements/thread over [192][32] tile,
// stored as bf16x2 in SMEM (SROWB=20 u32/row). MMA: 8 warps, all 6 pair-tiles,
// 2 k-steps of 16 per tile.
__global__ __launch_bounds__(256, 1)
void gram_tc(const float* __restrict__ x,
             const float* __restrict__ hgn,
             const float* __restrict__ lmda,
             const int* __restrict__ domain,
             const int* __restrict__ drand,
             float* __restrict__ out) {
    extern __shared__ unsigned sbuf[];   // 2 * BUFB
    int tid = threadIdx.x;
    int ks = blockIdx.x;
    long kbase = (long)ks * 768;

    // loader: element i covers rows [32i, 32i+32); row = e>>3, quad q = e&7
    const float* p[6];
    int soff[6];
    #pragma unroll
    for (int i = 0; i < 6; i++) {
        int e = tid + 256 * i;
        int row = e >> 3, q = e & 7;
        const float* src;
        if (row < 128) src = x + (size_t)(row & 63) * KDIM;
        else           src = hgn + (size_t)(row - 128) * KDIM;
        p[i] = src + kbase + q * 4;
        soff[i] = row * SROWB + q * 2;
    }
    float  lmv[2];
    int    offm[2], offdx[2], offdh[2];
    float* outp[2];
    #pragma unroll
    for (int j = 0; j < 2; j++) {
        int e = tid + 256 * (2 + j);
        int row = e >> 3, q = e & 7, b = row - 64;
        lmv[j] = lmda[b];
        int ds = (domain[b] + drand[b]) & 3;
        offm[j]  = b * FF + q * 4;
        offdx[j] = ds * FF + q * 4;
        outp[j]  = out + (size_t)b * KDIM + kbase + q * 4;
    }
    #pragma unroll
    for (int j = 0; j < 2; j++) {
        int e = tid + 256 * (4 + j);
        int b = (e >> 3) - 128, q = e & 7;
        offdh[j] = domain[b] * FF + q * 4;
    }

    int wid = tid >> 5, lane = tid & 31;
    int wm = wid >> 2, wn = wid & 3;     // 2x4 warps over each 64x64 tile
    int lr = lane >> 2, lc = lane & 3;
    const int TI[NPAIR] = {0,0,0,1,1,2};
    const int TJ[NPAIR] = {0,1,2,1,2,2};
    float acc[NPAIR][2][2][4];
    #pragma unroll
    for (int pp = 0; pp < NPAIR; pp++)
        #pragma unroll
        for (int mt = 0; mt < 2; mt++)
            #pragma unroll
            for (int nt = 0; nt < 2; nt++)
                #pragma unroll
                for (int r = 0; r < 4; r++) acc[pp][mt][nt][r] = 0.f;

    float4 v[6];
    #pragma unroll
    for (int i = 0; i < 6; i++) v[i] = *(const float4*)(p[i]);

    for (int t = 0; t < NTILES; t++) {
        unsigned* bb = sbuf + (t & 1) * BUFB;
        int fo = t * 32;
        float4 w[6];
        w[0] = v[0]; w[1] = v[1];
        #pragma unroll
        for (int j = 0; j < 2; j++) {
            float4 xv = v[2 + j];
            float4 mu = *(const float4*)(g_mu  + offm[j]  + fo);
            float4 iv = *(const float4*)(g_inv + offm[j]  + fo);
            float4 nm = *(const float4*)(g_nm  + offdx[j] + fo);
            float4 sd = *(const float4*)(g_nsd + offdx[j] + fo);
            float l = lmv[j], il = 1.f - l;
            float4 xm;
            xm.x = l * xv.x + il * fmaf((xv.x - mu.x) * iv.x, sd.x, nm.x);
            xm.y = l * xv.y + il * fmaf((xv.y - mu.y) * iv.y, sd.y, nm.y);
            xm.z = l * xv.z + il * fmaf((xv.z - mu.z) * iv.z, sd.z, nm.z);
            xm.w = l * xv.w + il * fmaf((xv.w - mu.w) * iv.w, sd.w, nm.w);
            *(float4*)(outp[j] + fo) = xm;
            w[2 + j] = xm;
        }
        #pragma unroll
        for (int j = 0; j < 2; j++) {
            float4 nz = v[4 + j];
            float4 nm = *(const float4*)(g_nm  + offdh[j] + fo);
            float4 sd = *(const float4*)(g_nsd + offdh[j] + fo);
            float4 hg;
            hg.x = fmaf(sd.x, nz.x, nm.x);
            hg.y = fmaf(sd.y, nz.y, nm.y);
            hg.z = fmaf(sd.z, nz.z, nm.z);
            hg.w = fmaf(sd.w, nz.w, nm.w);
            w[4 + j] = hg;
        }
        // bf16 convert + STS.64
        #pragma unroll
        for (int i = 0; i < 6; i++) {
            uint2 u;
            u.x = bfx2(w[i].x, w[i].y);
            u.y = bfx2(w[i].z, w[i].w);
            *(uint2*)(&bb[soff[i]]) = u;
        }
        if (t + 1 < NTILES) {
            #pragma unroll
            for (int i = 0; i < 6; i++) v[i] = *(const float4*)(p[i] + (t + 1) * 32);
        }
        __syncthreads();
        const unsigned* S = bb;
        #pragma unroll
        for (int kk = 0; kk < 2; kk++) {          // 2 k-steps of 16
            int ku = kk * 8;                      // u32 units
            unsigned af[3][2][4], bfr[3][2][2];
            #pragma unroll
            for (int g = 0; g < 3; g++) {
                #pragma unroll
                for (int mt = 0; mt < 2; mt++) {
                    int r0 = g * 64 + wm * 32 + mt * 16 + lr;
                    af[g][mt][0] = S[r0 * SROWB + ku + lc];
                    af[g][mt][1] = S[(r0 + 8) * SROWB + ku + lc];
                    af[g][mt][2] = S[r0 * SROWB + ku + lc + 4];
                    af[g][mt][3] = S[(r0 + 8) * SROWB + ku + lc + 4];
                }
                #pragma unroll
                for (int nt = 0; nt < 2; nt++) {
                    int n0 = g * 64 + wn * 16 + nt * 8 + lr;
                    bfr[g][nt][0] = S[n0 * SROWB + ku + lc];
                    bfr[g][nt][1] = S[n0 * SROWB + ku + lc + 4];
                }
            }
            #pragma unroll
            for (int pp = 0; pp < NPAIR; pp++)
                #pragma unroll
                for (int mt = 0; mt < 2; mt++)
                    #pragma unroll
                    for (int nt = 0; nt < 2; nt++)
                        mma_bf16(acc[pp][mt][nt], af[TI[pp]][mt], bfr[TJ[pp]][nt]);
        }
        __syncthreads();
    }

    float* base = g_gpart + (size_t)ks * KSLAB;
    #pragma unroll
    for (int pp = 0; pp < NPAIR; pp++) {
        #pragma unroll
        for (int mt = 0; mt < 2; mt++) {
            #pragma unroll
            for (int nt = 0; nt < 2; nt++) {
                int r = wm * 32 + mt * 16 + lr;
                int c = wn * 16 + nt * 8 + lc * 2;
                float* dst = base + pp * PAIRSZ + r * 64 + c;
                *(float2*)dst = make_float2(acc[pp][mt][nt][0], acc[pp][mt][nt][1]);
                *(float2*)(dst + 8 * 64) = make_float2(acc[pp][mt][nt][2], acc[pp][mt][nt][3]);
            }
        }
    }
}

// split-K reduction stage 1: 129 partials -> 16 chunks (chunk 0 has 9, rest 8)
__global__ void reduceG1() {
    int i4 = (blockIdx.x * 256 + threadIdx.x) * 4;   // 24 x-blocks
    int c = blockIdx.y;                               // 0..15
    int p0 = (c == 0) ? 0 : 8 * c + 1;
    const float* src = g_gpart + (size_t)p0 * KSLAB + i4;
    float4 v[8];
    #pragma unroll
    for (int p = 0; p < 8; p++)
        v[p] = *(const float4*)(src + (size_t)p * KSLAB);
    if (c == 0) {
        float4 e = *(const float4*)(src + (size_t)8 * KSLAB);
        v[0].x += e.x; v[0].y += e.y; v[0].z += e.z; v[0].w += e.w;
    }
    #pragma unroll
    for (int p = 0; p < 4; p++) {
        v[p].x += v[p + 4].x; v[p].y += v[p + 4].y;
        v[p].z += v[p + 4].z; v[p].w += v[p + 4].w;
    }
    #pragma unroll
    for (int p = 0; p < 2; p++) {
        v[p].x += v[p + 2].x; v[p].y += v[p + 2].y;
        v[p].z += v[p + 2].z; v[p].w += v[p + 2].w;
    }
    v[0].x += v[1].x; v[0].y += v[1].y; v[0].z += v[1].z; v[0].w += v[1].w;
    *(float4*)(&g_part2[c][i4]) = v[0];
}

__global__ void reduceG2() {
    int idx = blockIdx.x * 256 + threadIdx.x;
    if (idx >= N3 * N3) return;
    int i = idx / N3, j = idx % N3;
    int ti = i >> 6, tj = j >> 6, li = i & 63, lj = j & 63;
    int a, b2, la, lb;
    if (ti <= tj) { a = ti; b2 = tj; la = li; lb = lj; }
    else          { a = tj; b2 = ti; la = lj; lb = li; }
    int pair = a * (5 - a) / 2 + b2;
    int o = pair * PAIRSZ + la * 64 + lb;
    float s = 0.f;
    #pragma unroll
    for (int c = 0; c < RCHUNK; c++) s += g_part2[c][o];
    g_G[idx] = s;
}

__global__ void lossA(const int* __restrict__ labels) {
    int i = (blockIdx.x * blockDim.x + threadIdx.x) >> 5;
    int lane = threadIdx.x & 31;
    int li = (i < 2 * BB) ? labels[i & 63] : -1;
    float sqi = g_G[i * N3 + i];
    float ap = -1e30f, an = 1e30f;
    #pragma unroll
    for (int jj = 0; jj < 6; jj++) {
        int j = lane + jj * 32;
        int lj = (j < 2 * BB) ? labels[j & 63] : -1;
        float d2 = sqi + g_G[j * N3 + j] - 2.f * g_G[i * N3 + j];
        float dd = sqrtf(fmaxf(d2, 1e-12f));
        if (li == lj) ap = fmaxf(ap, dd);
        else          an = fminf(an, dd);
    }
    #pragma unroll
    for (int o = 16; o > 0; o >>= 1) {
        ap = fmaxf(ap, __shfl_xor_sync(0xFFFFFFFFu, ap, o));
        an = fminf(an, __shfl_xor_sync(0xFFFFFFFFu, an, o));
    }
    if (lane == 0) {
        float z = ap - an;
        g_rowloss[i] = (z > 0.f) ? (z + log1pf(expf(-z))) : log1pf(expf(z));
    }
}

__global__ void lossB(float* __restrict__ out) {
    __shared__ float red[256];
    int t = threadIdx.x;
    red[t] = (t < N3) ? g_rowloss[t] : 0.f;
    __syncthreads();
    for (int st = 128; st > 0; st >>= 1) {
        if (t < st) red[t] += red[t + st];
        __syncthreads();
    }
    if (t == 0) out[LOSS_OFF] = red[0] / (float)N3;
}

extern "C" void kernel_launch(void* const* d_in, const int* in_sizes, int n_in,
                              void* d_out, int out_size) {
    const float* x        = (const float*)d_in[0];
    const float* lmda     = (const float*)d_in[1];
    const float* mean_buf = (const float*)d_in[2];
    const float* var_buf  = (const float*)d_in[3];
    const float* hgn      = (const float*)d_in[4];
    const int*   labels   = (const int*)d_in[5];
    const int*   domain   = (const int*)d_in[6];
    const int*   d_rand   = (const int*)d_in[7];
    float* out = (float*)d_out;

    int smem_sz = 2 * BUFB * (int)sizeof(unsigned);   // 30720
    cudaFuncSetAttribute(gram_tc, cudaFuncAttributeMaxDynamicSharedMemorySize, smem_sz);

    dim3 ga(BB * 3, 4);
    stageA1<<<ga, 256>>>(x);
    stageAB<<<FF / 64, 256>>>(mean_buf, var_buf, domain, out);
    gram_tc<<<KSPLIT, 256, smem_sz>>>(x, hgn, lmda, domain, d_rand, out);
    dim3 gr(KSLAB / 1024, RCHUNK);
    reduceG1<<<gr, 256>>>();
    reduceG2<<<(N3 * N3 + 255) / 256, 256>>>();
    lossA<<<N3 / 8, 256>>>(labels);
    lossB<<<1, 256>>>(out);
}

// round 13
// speedup vs baseline: 1.3444x; 1.1698x over previous
#include <cuda_runtime.h>

#define BB 64
#define SS 129
#define FF 768
#define DD 4
#define KDIM (SS*FF)
#define N3 (3*BB)
#define MOM 0.9f
#define EPSV 1e-6f

#define XMIX_N (BB*SS*FF)
#define LOSS_OFF XMIX_N
#define NM_OFF (XMIX_N + 1)
#define NV_OFF (NM_OFF + DD*FF)

// gram config: bf16 tiles, split over all 148 SMs
#define KSPLIT 148
#define SROWB 20                    // u32 (bf16x2) units per 32-k row, padded
#define BUFB (N3*SROWB)             // 3840 u32 per buffer
#define NPAIR 6
#define PAIRSZ 4096
#define KSLAB (NPAIR*PAIRSZ)
#define RCHUNK 16

__device__ float g_pA1[4][BB*FF];
__device__ float g_pA2[4][BB*FF];
__device__ float g_xA[BB*FF];       // xmix = A*x + B
__device__ float g_xB[BB*FF];
__device__ float g_nm[DD*FF];
__device__ float g_nsd[DD*FF];
__device__ float g_gpart[KSPLIT*KSLAB];
__device__ float g_part2[RCHUNK][KSLAB];
__device__ float g_G[N3*N3];
__device__ float g_rowloss[N3];

__device__ __forceinline__ unsigned bfx2(float lo, float hi) {
    unsigned r;
    asm("cvt.rn.bf16x2.f32 %0, %1, %2;" : "=r"(r) : "f"(hi), "f"(lo));
    return r;
}

__device__ __forceinline__ void mma_bf16(float* d, const unsigned* a, const unsigned* b) {
    asm volatile("mma.sync.aligned.m16n8k16.row.col.f32.bf16.bf16.f32 "
        "{%0,%1,%2,%3},{%4,%5,%6,%7},{%8,%9},{%0,%1,%2,%3};"
        : "+f"(d[0]), "+f"(d[1]), "+f"(d[2]), "+f"(d[3])
        : "r"(a[0]), "r"(a[1]), "r"(a[2]), "r"(a[3]), "r"(b[0]), "r"(b[1]));
}

__global__ void stageA1(const float* __restrict__ x) {
    int bf = blockIdx.x;
    int seg = blockIdx.y;
    int b = bf / 3;
    int f = (bf % 3) * 256 + threadIdx.x;
    int s0 = (seg == 0) ? 0 : 33 + 32 * (seg - 1);
    int s1 = 33 + 32 * seg;
    const float* p = x + (size_t)b * KDIM + f;
    float sa = 0.f, sb2 = 0.f, sc = 0.f, sd2 = 0.f;
    int ss = s0;
    for (; ss + 1 < s1; ss += 2) {
        float v0 = p[(size_t)ss * FF];
        float v1 = p[(size_t)(ss + 1) * FF];
        sa += v0; sb2 += v0 * v0;
        sc += v1; sd2 += v1 * v1;
    }
    if (ss < s1) { float v = p[(size_t)ss * FF]; sa += v; sb2 += v * v; }
    int o = b * FF + f;
    g_pA1[seg][o] = sa + sc;
    g_pA2[seg][o] = sb2 + sd2;
}

// combine partials -> instance stats -> domain EMA -> xmix A/B coefficients
__global__ void stageAB(const float* __restrict__ mean_buf,
                        const float* __restrict__ var_buf,
                        const int* __restrict__ domain,
                        const int* __restrict__ drand,
                        const float* __restrict__ lmda,
                        float* __restrict__ out) {
    __shared__ float s1s[64][65];
    __shared__ float s2s[64][65];
    __shared__ float nm_s[4][64];
    __shared__ float sd_s[4][64];
    __shared__ int doms[64];
    __shared__ int dss[64];
    __shared__ float lms[64];
    int tid = threadIdx.x;
    int f0 = blockIdx.x * 64;
    if (tid < 64) {
        doms[tid] = domain[tid];
        dss[tid] = (domain[tid] + drand[tid]) & 3;
        lms[tid] = lmda[tid];
    }
    __syncthreads();
    #pragma unroll
    for (int i = 0; i < 16; i++) {
        int e = tid + 256 * i;
        int b = e >> 6, f = e & 63;
        int idx = b * FF + f0 + f;
        float s  = g_pA1[0][idx] + g_pA1[1][idx] + g_pA1[2][idx] + g_pA1[3][idx];
        float s2 = g_pA2[0][idx] + g_pA2[1][idx] + g_pA2[2][idx] + g_pA2[3][idx];
        s1s[b][f] = s;
        s2s[b][f] = s2;
    }
    __syncthreads();
    {
        int d = tid >> 6, f = tid & 63;
        float s1 = 0.f, s2 = 0.f;
        int nb = 0;
        #pragma unroll 8
        for (int b = 0; b < BB; b++) {
            if (doms[b] == d) {
                nb++;
                s1 += s1s[b][f];
                s2 += s2s[b][f];
            }
        }
        float n = (float)nb * (float)SS;
        float mu = s1 / fmaxf(n, 1.f);
        float var = (s2 - n * mu * mu) / fmaxf(n - 1.f, 1.f);
        int idx = d * FF + f0 + f;
        float nm, nv;
        if (nb > 0) {
            nm = MOM * mean_buf[idx] + (1.f - MOM) * mu;
            nv = MOM * var_buf[idx] + (1.f - MOM) * var;
        } else {
            nm = mean_buf[idx];
            nv = var_buf[idx];
        }
        out[NM_OFF + idx] = nm;
        out[NV_OFF + idx] = nv;
        float sd = sqrtf(nv + EPSV);
        g_nm[idx] = nm;
        g_nsd[idx] = sd;
        nm_s[d][f] = nm;
        sd_s[d][f] = sd;
    }
    __syncthreads();
    #pragma unroll
    for (int i = 0; i < 16; i++) {
        int e = tid + 256 * i;
        int b = e >> 6, f = e & 63;
        float s = s1s[b][f], s2 = s2s[b][f];
        float mu = s / (float)SS;
        float var = (s2 - (float)SS * mu * mu) / (float)(SS - 1);
        float inv = rsqrtf(var + EPSV);
        int ds = dss[b];
        float lm = lms[b], il = 1.f - lm;
        float isd = inv * sd_s[ds][f];
        int idx = b * FF + f0 + f;
        g_xA[idx] = lm + il * isd;
        g_xB[idx] = il * (nm_s[ds][f] - mu * isd);
    }
}

// fused gram (bf16 mma m16n8k16) + xmix + hg. 148 CTAs x 256 threads.
__global__ __launch_bounds__(256, 1)
void gram_tc(const float* __restrict__ x,
             const float* __restrict__ hgn,
             const int* __restrict__ domain,
             float* __restrict__ out) {
    extern __shared__ unsigned sbuf[];   // 2 * BUFB
    int tid = threadIdx.x;
    int ks = blockIdx.x;
    int start = ks * 20 + (ks < 136 ? ks : 136);
    int ntile = (ks < 136) ? 21 : 20;
    long kbase = (long)start * 32;

    // loader: element i covers rows [32i, 32i+32); row = e>>3, quad q = e&7
    const float* p[6];
    int soff[6];
    #pragma unroll
    for (int i = 0; i < 6; i++) {
        int e = tid + 256 * i;
        int row = e >> 3, q = e & 7;
        const float* src;
        if (row < 128) src = x + (size_t)(row & 63) * KDIM;
        else           src = hgn + (size_t)(row - 128) * KDIM;
        p[i] = src + kbase + q * 4;
        soff[i] = row * SROWB + q * 2;
    }
    int offm[2], offdh[2];
    float* outp[2];
    #pragma unroll
    for (int j = 0; j < 2; j++) {
        int e = tid + 256 * (2 + j);
        int row = e >> 3, q = e & 7, b = row - 64;
        offm[j] = b * FF + q * 4;
        outp[j] = out + (size_t)b * KDIM + kbase + q * 4;
    }
    #pragma unroll
    for (int j = 0; j < 2; j++) {
        int e = tid + 256 * (4 + j);
        int b = (e >> 3) - 128, q = e & 7;
        offdh[j] = domain[b] * FF + q * 4;
    }

    int wid = tid >> 5, lane = tid & 31;
    int wm = wid >> 2, wn = wid & 3;
    int lr = lane >> 2, lc = lane & 3;
    const int TI[NPAIR] = {0,0,0,1,1,2};
    const int TJ[NPAIR] = {0,1,2,1,2,2};
    float acc[NPAIR][2][2][4];
    #pragma unroll
    for (int pp = 0; pp < NPAIR; pp++)
        #pragma unroll
        for (int mt = 0; mt < 2; mt++)
            #pragma unroll
            for (int nt = 0; nt < 2; nt++)
                #pragma unroll
                for (int r = 0; r < 4; r++) acc[pp][mt][nt][r] = 0.f;

    float4 v[6];
    #pragma unroll
    for (int i = 0; i < 6; i++) v[i] = *(const float4*)(p[i]);
    int fm = start % 24;

    for (int t = 0; t < ntile; t++) {
        unsigned* bb = sbuf + (t & 1) * BUFB;
        int fo = fm * 32;
        fm = (fm + 1 == 24) ? 0 : fm + 1;
        float4 w[6];
        w[0] = v[0]; w[1] = v[1];
        // xmix rows via precomputed A/B
        #pragma unroll
        for (int j = 0; j < 2; j++) {
            float4 xv = v[2 + j];
            float4 A = *(const float4*)(g_xA + offm[j] + fo);
            float4 Bc = *(const float4*)(g_xB + offm[j] + fo);
            float4 xm;
            xm.x = fmaf(A.x, xv.x, Bc.x);
            xm.y = fmaf(A.y, xv.y, Bc.y);
            xm.z = fmaf(A.z, xv.z, Bc.z);
            xm.w = fmaf(A.w, xv.w, Bc.w);
            *(float4*)(outp[j] + t * 32) = xm;
            w[2 + j] = xm;
        }
        // hg rows
        #pragma unroll
        for (int j = 0; j < 2; j++) {
            float4 nz = v[4 + j];
            float4 nm = *(const float4*)(g_nm  + offdh[j] + fo);
            float4 sd = *(const float4*)(g_nsd + offdh[j] + fo);
            float4 hg;
            hg.x = fmaf(sd.x, nz.x, nm.x);
            hg.y = fmaf(sd.y, nz.y, nm.y);
            hg.z = fmaf(sd.z, nz.z, nm.z);
            hg.w = fmaf(sd.w, nz.w, nm.w);
            w[4 + j] = hg;
        }
        #pragma unroll
        for (int i = 0; i < 6; i++) {
            uint2 u;
            u.x = bfx2(w[i].x, w[i].y);
            u.y = bfx2(w[i].z, w[i].w);
            *(uint2*)(&bb[soff[i]]) = u;
        }
        if (t + 1 < ntile) {
            #pragma unroll
            for (int i = 0; i < 6; i++) v[i] = *(const float4*)(p[i] + (t + 1) * 32);
        }
        __syncthreads();
        const unsigned* S = bb;
        #pragma unroll
        for (int kk = 0; kk < 2; kk++) {
            int ku = kk * 8;
            unsigned af[3][2][4], bfr[3][2][2];
            #pragma unroll
            for (int g = 0; g < 3; g++) {
                #pragma unroll
                for (int mt = 0; mt < 2; mt++) {
                    int r0 = g * 64 + wm * 32 + mt * 16 + lr;
                    af[g][mt][0] = S[r0 * SROWB + ku + lc];
                    af[g][mt][1] = S[(r0 + 8) * SROWB + ku + lc];
                    af[g][mt][2] = S[r0 * SROWB + ku + lc + 4];
                    af[g][mt][3] = S[(r0 + 8) * SROWB + ku + lc + 4];
                }
                #pragma unroll
                for (int nt = 0; nt < 2; nt++) {
                    int n0 = g * 64 + wn * 16 + nt * 8 + lr;
                    bfr[g][nt][0] = S[n0 * SROWB + ku + lc];
                    bfr[g][nt][1] = S[n0 * SROWB + ku + lc + 4];
                }
            }
            #pragma unroll
            for (int pp = 0; pp < NPAIR; pp++)
                #pragma unroll
                for (int mt = 0; mt < 2; mt++)
                    #pragma unroll
                    for (int nt = 0; nt < 2; nt++)
                        mma_bf16(acc[pp][mt][nt], af[TI[pp]][mt], bfr[TJ[pp]][nt]);
        }
        // single sync per tile: double-buffered, STS(t+2) is warp-ordered
        // after own MMA(t) and barrier-ordered after all MMA(t).
    }

    float* base = g_gpart + (size_t)ks * KSLAB;
    #pragma unroll
    for (int pp = 0; pp < NPAIR; pp++) {
        #pragma unroll
        for (int mt = 0; mt < 2; mt++) {
            #pragma unroll
            for (int nt = 0; nt < 2; nt++) {
                int r = wm * 32 + mt * 16 + lr;
                int c = wn * 16 + nt * 8 + lc * 2;
                float* dst = base + pp * PAIRSZ + r * 64 + c;
                *(float2*)dst = make_float2(acc[pp][mt][nt][0], acc[pp][mt][nt][1]);
                *(float2*)(dst + 8 * 64) = make_float2(acc[pp][mt][nt][2], acc[pp][mt][nt][3]);
            }
        }
    }
}

// split-K reduction stage 1: 148 partials -> 16 chunks (first 4 have 10, rest 9)
__global__ void reduceG1() {
    int i4 = (blockIdx.x * 256 + threadIdx.x) * 4;
    int c = blockIdx.y;
    int p0 = c * 9 + (c < 4 ? c : 4);
    const float* src = g_gpart + (size_t)p0 * KSLAB + i4;
    float4 v[9];
    #pragma unroll
    for (int p = 0; p < 9; p++)
        v[p] = *(const float4*)(src + (size_t)p * KSLAB);
    if (c < 4) {
        float4 e = *(const float4*)(src + (size_t)9 * KSLAB);
        v[0].x += e.x; v[0].y += e.y; v[0].z += e.z; v[0].w += e.w;
    }
    #pragma unroll
    for (int p = 0; p < 4; p++) {
        v[p].x += v[p + 4].x; v[p].y += v[p + 4].y;
        v[p].z += v[p + 4].z; v[p].w += v[p + 4].w;
    }
    v[0].x += v[8].x; v[0].y += v[8].y; v[0].z += v[8].z; v[0].w += v[8].w;
    #pragma unroll
    for (int p = 0; p < 2; p++) {
        v[p].x += v[p + 2].x; v[p].y += v[p + 2].y;
        v[p].z += v[p + 2].z; v[p].w += v[p + 2].w;
    }
    v[0].x += v[1].x; v[0].y += v[1].y; v[0].z += v[1].z; v[0].w += v[1].w;
    *(float4*)(&g_part2[c][i4]) = v[0];
}

__global__ void reduceG2() {
    int idx = blockIdx.x * 256 + threadIdx.x;
    if (idx >= N3 * N3) return;
    int i = idx / N3, j = idx % N3;
    int ti = i >> 6, tj = j >> 6, li = i & 63, lj = j & 63;
    int a, b2, la, lb;
    if (ti <= tj) { a = ti; b2 = tj; la = li; lb = lj; }
    else          { a = tj; b2 = ti; la = lj; lb = li; }
    int pair = a * (5 - a) / 2 + b2;
    int o = pair * PAIRSZ + la * 64 + lb;
    float s = 0.f;
    #pragma unroll
    for (int c = 0; c < RCHUNK; c++) s += g_part2[c][o];
    g_G[idx] = s;
}

__global__ void lossA(const int* __restrict__ labels) {
    int i = (blockIdx.x * blockDim.x + threadIdx.x) >> 5;
    int lane = threadIdx.x & 31;
    int li = (i < 2 * BB) ? labels[i & 63] : -1;
    float sqi = g_G[i * N3 + i];
    float ap = -1e30f, an = 1e30f;
    #pragma unroll
    for (int jj = 0; jj < 6; jj++) {
        int j = lane + jj * 32;
        int lj = (j < 2 * BB) ? labels[j & 63] : -1;
        float d2 = sqi + g_G[j * N3 + j] - 2.f * g_G[i * N3 + j];
        float dd = sqrtf(fmaxf(d2, 1e-12f));
        if (li == lj) ap = fmaxf(ap, dd);
        else          an = fminf(an, dd);
    }
    #pragma unroll
    for (int o = 16; o > 0; o >>= 1) {
        ap = fmaxf(ap, __shfl_xor_sync(0xFFFFFFFFu, ap, o));
        an = fminf(an, __shfl_xor_sync(0xFFFFFFFFu, an, o));
    }
    if (lane == 0) {
        float z = ap - an;
        g_rowloss[i] = (z > 0.f) ? (z + log1pf(expf(-z))) : log1pf(expf(z));
    }
}

__global__ void lossB(float* __restrict__ out) {
    __shared__ float red[256];
    int t = threadIdx.x;
    red[t] = (t < N3) ? g_rowloss[t] : 0.f;
    __syncthreads();
    for (int st = 128; st > 0; st >>= 1) {
        if (t < st) red[t] += red[t + st];
        __syncthreads();
    }
    if (t == 0) out[LOSS_OFF] = red[0] / (float)N3;
}

extern "C" void kernel_launch(void* const* d_in, const int* in_sizes, int n_in,
                              void* d_out, int out_size) {
    const float* x        = (const float*)d_in[0];
    const float* lmda     = (const float*)d_in[1];
    const float* mean_buf = (const float*)d_in[2];
    const float* var_buf  = (const float*)d_in[3];
    const float* hgn      = (const float*)d_in[4];
    const int*   labels   = (const int*)d_in[5];
    const int*   domain   = (const int*)d_in[6];
    const int*   d_rand   = (const int*)d_in[7];
    float* out = (float*)d_out;

    int smem_sz = 2 * BUFB * (int)sizeof(unsigned);   // 30720
    cudaFuncSetAttribute(gram_tc, cudaFuncAttributeMaxDynamicSharedMemorySize, smem_sz);

    dim3 ga(BB * 3, 4);
    stageA1<<<ga, 256>>>(x);
    stageAB<<<FF / 64, 256>>>(mean_buf, var_buf, domain, d_rand, lmda, out);
    gram_tc<<<KSPLIT, 256, smem_sz>>>(x, hgn, domain, out);
    dim3 gr(KSLAB / 1024, RCHUNK);
    reduceG1<<<gr, 256>>>();
    reduceG2<<<(N3 * N3 + 255) / 256, 256>>>();
    lossA<<<N3 / 8, 256>>>(labels);
    lossB<<<1, 256>>>(out);
}